// round 16
// baseline (speedup 1.0000x reference)
#include <cuda_runtime.h>
#include <cuda_fp16.h>
#include <cstdint>

// ============================================================================
// CIN fully fused (3 layers + d-reduce, ONE kernel), mma.sync m16n8k16 FP16.
// R15: = R14 (2-term split, 128-K chunks) + MMA issue order term-major:
// same-accumulator rewrite distance 2 -> 16 MMAs to cover dependent-HMMA
// latency (suspected ~18% mainloop inflation).
// ============================================================================

#define CIN_B   2048
#define CIN_F0  64
#define CIN_D   16
#define CIN_FN  128
#define CIN_M   (CIN_B * CIN_D)   // 32768

// Per 128-K chunk (hi only): 64 kpairs x 136 u32 = 8704 u32 = 34816 B
#define CH_U32  8704
#define CH_BYTES 34816u
#define TOTAL_CHUNKS 160          // 32 (l0) + 64 (l1) + 64 (l2)

// Device scratch
__device__ float    g_xT[CIN_M * CIN_F0];                    // 8 MB
__device__ uint32_t g_wp[(32 + 64 + 64) * CH_U32];           // 5.6 MB fp16 pairs

// ---------------------------------------------------------------------------
__device__ __forceinline__ uint32_t smem_u32(const void* p) {
    uint32_t a;
    asm("{ .reg .u64 t; cvta.to.shared.u64 t, %1; cvt.u32.u64 %0, t; }" : "=r"(a) : "l"(p));
    return a;
}
__device__ __forceinline__ void mbar_init(uint32_t mbar, uint32_t cnt) {
    asm volatile("mbarrier.init.shared.b64 [%0], %1;" :: "r"(mbar), "r"(cnt) : "memory");
}
__device__ __forceinline__ void mbar_expect_tx(uint32_t mbar, uint32_t bytes) {
    asm volatile("mbarrier.arrive.expect_tx.shared.b64 _, [%0], %1;"
                 :: "r"(mbar), "r"(bytes) : "memory");
}
__device__ __forceinline__ void mbar_wait(uint32_t mbar, uint32_t parity) {
    uint32_t done = 0;
    while (!done) {
        asm volatile(
            "{\n\t.reg .pred p;\n\t"
            "mbarrier.try_wait.parity.shared.b64 p, [%1], %2;\n\t"
            "selp.b32 %0, 1, 0, p;\n\t}"
            : "=r"(done) : "r"(mbar), "r"(parity) : "memory");
    }
}
__device__ __forceinline__ void bulk_g2s(uint32_t dst, const void* src, uint32_t bytes,
                                         uint32_t mbar) {
    asm volatile(
        "cp.async.bulk.shared::cluster.global.mbarrier::complete_tx::bytes "
        "[%0], [%1], %2, [%3];"
        :: "r"(dst), "l"(src), "r"(bytes), "r"(mbar) : "memory");
}
__device__ __forceinline__ void mma_f16(float& d0, float& d1, float& d2, float& d3,
                                        uint32_t a0, uint32_t a1, uint32_t a2, uint32_t a3,
                                        uint32_t b0, uint32_t b1) {
    asm volatile(
        "mma.sync.aligned.m16n8k16.row.col.f32.f16.f16.f32 "
        "{%0,%1,%2,%3}, {%4,%5,%6,%7}, {%8,%9}, {%0,%1,%2,%3};"
        : "+f"(d0), "+f"(d1), "+f"(d2), "+f"(d3)
        : "r"(a0), "r"(a1), "r"(a2), "r"(a3), "r"(b0), "r"(b1));
}
__device__ __forceinline__ void pack_split(float v0, float v1, uint32_t& hi, uint32_t& lo) {
    __half2 h = __floats2half2_rn(v0, v1);
    float2 back = __half22float2(h);
    __half2 l = __floats2half2_rn(v0 - back.x, v1 - back.y);
    hi = *reinterpret_cast<uint32_t*>(&h);
    lo = *reinterpret_cast<uint32_t*>(&l);
}
__device__ __forceinline__ uint32_t pack_hi(float v0, float v1) {
    __half2 h = __floats2half2_rn(v0, v1);
    return *reinterpret_cast<uint32_t*>(&h);
}
__device__ __forceinline__ const uint32_t* chunk_src(
    const uint32_t* w0, const uint32_t* w1, const uint32_t* w2, int gch) {
    if (gch < 32) return w0 + (size_t)gch * CH_U32;
    if (gch < 96) return w1 + (size_t)(gch - 32) * CH_U32;
    return w2 + (size_t)(gch - 96) * CH_U32;
}

// ---------------------------------------------------------------------------
// Prep: x [B, F0, D] -> xT [(b*16+d), 64]
__global__ void k_xT(const float* __restrict__ x, float* __restrict__ xT) {
    int o = blockIdx.x * 256 + threadIdx.x;
    if (o >= CIN_M * CIN_F0) return;
    int i = o & 63;
    int m = o >> 6;
    int b = m >> 4;
    int d = m & 15;
    xT[o] = x[(b * CIN_F0 + i) * CIN_D + d];
}

// Prep: W [F0*Fi, 128] -> fp16 (hi only) in 128-K' chunks.
__global__ void k_wp(const float* __restrict__ W, uint32_t* __restrict__ dst, int Fi) {
    int total = CIN_F0 * Fi * 128 / 2;   // one half2 per item
    for (int o = blockIdx.x * 256 + threadIdx.x; o < total; o += gridDim.x * 256) {
        int n = o & 127;
        int gp = o >> 7;                 // global kpair
        int s = gp >> 6;
        int p = gp & 63;
        int k0 = gp * 2;
        float v0 = W[(size_t)k0 * 128 + n];
        float v1 = W[(size_t)(k0 + 1) * 128 + n];
        dst[(size_t)s * CH_U32 + p * 136 + n] = pack_hi(v0, v1);
    }
}

// ---------------------------------------------------------------------------
// MMA micro-step: one k16 group, term-major issue order.
// Same-accumulator rewrite distance = 16 MMAs (covers dependent-HMMA latency).
__device__ __forceinline__ void mma_group(
    const uint32_t* __restrict__ HsHi, const uint32_t* __restrict__ HsLo,
    const uint32_t* __restrict__ Bc, int akp0, int bkp0,
    int row0, int g, int wn, float t[2][8][4]) {
    uint32_t ah[2][4], al[2][4];
#pragma unroll
    for (int mt = 0; mt < 2; mt++) {
        int r = row0 + mt * 16;
        ah[mt][0] = HsHi[akp0 * 136 + r];
        ah[mt][1] = HsHi[akp0 * 136 + r + 8];
        ah[mt][2] = HsHi[(akp0 + 4) * 136 + r];
        ah[mt][3] = HsHi[(akp0 + 4) * 136 + r + 8];
        al[mt][0] = HsLo[akp0 * 136 + r];
        al[mt][1] = HsLo[akp0 * 136 + r + 8];
        al[mt][2] = HsLo[(akp0 + 4) * 136 + r];
        al[mt][3] = HsLo[(akp0 + 4) * 136 + r + 8];
    }
    // Preload all B fragments
    uint32_t b0[8], b1[8];
    const int p0 = bkp0 * 136;
    const int p1 = p0 + 4 * 136;
#pragma unroll
    for (int nt = 0; nt < 8; ++nt) {
        int ncol = wn * 64 + nt * 8 + g;
        b0[nt] = Bc[p0 + ncol];
        b1[nt] = Bc[p1 + ncol];
    }
    // Term-major: all nt for (mt0,ah), (mt1,ah), (mt0,al), (mt1,al)
#pragma unroll
    for (int nt = 0; nt < 8; ++nt)
        mma_f16(t[0][nt][0], t[0][nt][1], t[0][nt][2], t[0][nt][3],
                ah[0][0], ah[0][1], ah[0][2], ah[0][3], b0[nt], b1[nt]);
#pragma unroll
    for (int nt = 0; nt < 8; ++nt)
        mma_f16(t[1][nt][0], t[1][nt][1], t[1][nt][2], t[1][nt][3],
                ah[1][0], ah[1][1], ah[1][2], ah[1][3], b0[nt], b1[nt]);
#pragma unroll
    for (int nt = 0; nt < 8; ++nt)
        mma_f16(t[0][nt][0], t[0][nt][1], t[0][nt][2], t[0][nt][3],
                al[0][0], al[0][1], al[0][2], al[0][3], b0[nt], b1[nt]);
#pragma unroll
    for (int nt = 0; nt < 8; ++nt)
        mma_f16(t[1][nt][0], t[1][nt][1], t[1][nt][2], t[1][nt][3],
                al[1][0], al[1][1], al[1][2], al[1][3], b0[nt], b1[nt]);
}

__device__ __forceinline__ void zero_t(float t[2][8][4]) {
#pragma unroll
    for (int mt = 0; mt < 2; mt++)
#pragma unroll
        for (int nt = 0; nt < 8; nt++)
#pragma unroll
            for (int q = 0; q < 4; q++) t[mt][nt][q] = 0.f;
}

__device__ __forceinline__ void fold_t(
    const float* __restrict__ xs, int i, int row0,
    float t[2][8][4], float hacc[2][8][4]) {
    float xv0 = xs[row0 * 68 + i];
    float xv1 = xs[(row0 + 8) * 68 + i];
    float xv2 = xs[(row0 + 16) * 68 + i];
    float xv3 = xs[(row0 + 24) * 68 + i];
#pragma unroll
    for (int nt = 0; nt < 8; nt++) {
        hacc[0][nt][0] += xv0 * t[0][nt][0];
        hacc[0][nt][1] += xv0 * t[0][nt][1];
        hacc[0][nt][2] += xv1 * t[0][nt][2];
        hacc[0][nt][3] += xv1 * t[0][nt][3];
        hacc[1][nt][0] += xv2 * t[1][nt][0];
        hacc[1][nt][1] += xv2 * t[1][nt][1];
        hacc[1][nt][2] += xv3 * t[1][nt][2];
        hacc[1][nt][3] += xv3 * t[1][nt][3];
    }
}

// Ring step: wait chunk gch, barrier, prefetch gch+2.
__device__ __forceinline__ const uint32_t* ring_step(
    const uint32_t* __restrict__ w0, const uint32_t* __restrict__ w1,
    const uint32_t* __restrict__ w2,
    uint32_t sb, uint32_t bs_u32, const uint32_t* __restrict__ Bp,
    int gch, int tid) {
    const int slot = gch % 3;
    mbar_wait(sb + slot * 8, (gch / 3) & 1);
    __syncthreads();
    if (tid == 0 && gch + 2 < TOTAL_CHUNKS) {
        const int ns = (gch + 2) % 3;
        mbar_expect_tx(sb + ns * 8, CH_BYTES);
        bulk_g2s(bs_u32 + ns * CH_BYTES, chunk_src(w0, w1, w2, gch + 2),
                 CH_BYTES, sb + ns * 8);
    }
    return Bp + slot * CH_U32;
}

// ---------------------------------------------------------------------------
// Fused kernel: 256 threads = 8 warps (4 wm x 2 wn), tile 128m x 128n.
// SMEM: [0..64) mbar[3] | HsHi[64][136] HsLo[64][136] | xs[128][68] | 3 B slots
__global__ __launch_bounds__(256, 1) void cin_fused(
    const float* __restrict__ xT,
    const uint32_t* __restrict__ w0,
    const uint32_t* __restrict__ w1,
    const uint32_t* __restrict__ w2,
    float* __restrict__ out) {
    extern __shared__ char smem[];
    constexpr int HB = 64;
    constexpr int HS_U32 = 64 * 136;
    constexpr int XB = HB + 2 * HS_U32 * 4;
    constexpr int BB = XB + 128 * 68 * 4;

    uint32_t* HsHi = reinterpret_cast<uint32_t*>(smem + HB);
    uint32_t* HsLo = HsHi + HS_U32;
    float* xs = reinterpret_cast<float*>(smem + XB);
    uint32_t* Bp = reinterpret_cast<uint32_t*>(smem + BB);
    const uint32_t sb = smem_u32(smem);
    const uint32_t bs_u32 = sb + BB;

    const int tid = threadIdx.x;
    const int lane = tid & 31;
    const int wid = tid >> 5;
    const int g = lane >> 2;
    const int c = lane & 3;
    const int wm = wid >> 1;
    const int wn = wid & 1;
    const int m0 = blockIdx.x * 128;
    const int row0 = wm * 32 + g;

    if (tid == 0) {
        mbar_init(sb + 0, 1);
        mbar_init(sb + 8, 1);
        mbar_init(sb + 16, 1);
    }
    __syncthreads();
    if (tid == 0) {
#pragma unroll
        for (int pc = 0; pc < 2; ++pc) {
            mbar_expect_tx(sb + pc * 8, CH_BYTES);
            bulk_g2s(bs_u32 + pc * CH_BYTES, chunk_src(w0, w1, w2, pc),
                     CH_BYTES, sb + pc * 8);
        }
    }

    // Layer-0 Hs from xT (KP=32) + xs tile
    for (int idx = tid; idx < 128 * 32; idx += 256) {
        int p = idx & 31;
        int m = idx >> 5;
        float2 v = *reinterpret_cast<const float2*>(xT + (size_t)(m0 + m) * 64 + 2 * p);
        uint32_t hi, lo;
        pack_split(v.x, v.y, hi, lo);
        HsHi[p * 136 + m] = hi;
        HsLo[p * 136 + m] = lo;
    }
    {
        const float4* Xg = reinterpret_cast<const float4*>(xT + (size_t)m0 * 64);
        for (int idx = tid; idx < 128 * 16; idx += 256) {
            int m = idx >> 4;
            int seg = idx & 15;
            *reinterpret_cast<float4*>(xs + m * 68 + seg * 4) = Xg[idx];
        }
    }
    __syncthreads();

    float hacc[2][8][4];
    float t[2][8][4];
    int gch = 0;

    for (int layer = 0; layer < 3; ++layer) {
#pragma unroll
        for (int mt = 0; mt < 2; mt++)
#pragma unroll
            for (int nt = 0; nt < 8; nt++)
#pragma unroll
                for (int q = 0; q < 4; q++) hacc[mt][nt][q] = 0.f;

        if (layer == 0) {
            // FI=64: each 128-K chunk covers TWO i values
            for (int s = 0; s < 32; ++s, ++gch) {
                const uint32_t* Bc = ring_step(w0, w1, w2, sb, bs_u32, Bp, gch, tid);
#pragma unroll
                for (int half = 0; half < 2; ++half) {
                    zero_t(t);
#pragma unroll
                    for (int ks = 0; ks < 4; ++ks) {
                        int akp0 = ks * 8 + c;
                        int bkp0 = half * 32 + ks * 8 + c;
                        mma_group(HsHi, HsLo, Bc, akp0, bkp0, row0, g, wn, t);
                    }
                    fold_t(xs, 2 * s + half, row0, t, hacc);
                }
            }
        } else {
            // FI=128: one chunk per i
            for (int s = 0; s < 64; ++s, ++gch) {
                const uint32_t* Bc = ring_step(w0, w1, w2, sb, bs_u32, Bp, gch, tid);
                zero_t(t);
#pragma unroll
                for (int ks = 0; ks < 8; ++ks) {
                    int kp0 = ks * 8 + c;
                    mma_group(HsHi, HsLo, Bc, kp0, kp0, row0, g, wn, t);
                }
                fold_t(xs, s, row0, t, hacc);
            }
        }

        // out[b, layer*128+n] = sum_d
#pragma unroll
        for (int mt = 0; mt < 2; mt++) {
            int b = (m0 >> 4) + wm * 2 + mt;
#pragma unroll
            for (int nt = 0; nt < 8; nt++) {
                float v0 = hacc[mt][nt][0] + hacc[mt][nt][2];
                float v1 = hacc[mt][nt][1] + hacc[mt][nt][3];
#pragma unroll
                for (int sh = 4; sh <= 16; sh <<= 1) {
                    v0 += __shfl_xor_sync(0xFFFFFFFFu, v0, sh);
                    v1 += __shfl_xor_sync(0xFFFFFFFFu, v1, sh);
                }
                if (g == 0) {
                    int col = wn * 64 + nt * 8 + 2 * c;
                    *reinterpret_cast<float2*>(out + (size_t)b * 384 + layer * 128 + col) =
                        make_float2(v0, v1);
                }
            }
        }

        // Rebuild Hs from hacc for next layer (KP=64)
        if (layer < 2) {
            __syncthreads();
#pragma unroll
            for (int mt = 0; mt < 2; mt++) {
                int r = row0 + mt * 16;
#pragma unroll
                for (int nt = 0; nt < 8; nt++) {
                    int p = wn * 32 + nt * 4 + c;
                    uint32_t hi, lo;
                    pack_split(hacc[mt][nt][0], hacc[mt][nt][1], hi, lo);
                    HsHi[p * 136 + r] = hi;
                    HsLo[p * 136 + r] = lo;
                    pack_split(hacc[mt][nt][2], hacc[mt][nt][3], hi, lo);
                    HsHi[p * 136 + r + 8] = hi;
                    HsLo[p * 136 + r + 8] = lo;
                }
            }
            __syncthreads();
        }
    }
}

// ---------------------------------------------------------------------------
extern "C" void kernel_launch(void* const* d_in, const int* in_sizes, int n_in,
                              void* d_out, int out_size) {
    const float* x  = (const float*)d_in[0];
    const float* W0 = (const float*)d_in[1];
    const float* W1 = (const float*)d_in[2];
    const float* W2 = (const float*)d_in[3];
    float* out = (float*)d_out;

    float* xT;
    uint32_t* wp;
    cudaGetSymbolAddress((void**)&xT, g_xT);
    cudaGetSymbolAddress((void**)&wp, g_wp);

    uint32_t* wp_0 = wp;                          // 32 chunks
    uint32_t* wp_1 = wp + (size_t)32 * CH_U32;    // 64 chunks
    uint32_t* wp_2 = wp_1 + (size_t)64 * CH_U32;  // 64 chunks

    // SMEM: 64 + 69632 (Hs) + 34816 (xs) + 104448 (3 slots) = 208,960 B
    const int smemF = 64 + (2 * 64 * 136 + 128 * 68) * 4 + 3 * CH_BYTES;
    cudaFuncSetAttribute(cin_fused, cudaFuncAttributeMaxDynamicSharedMemorySize, smemF);

    // Prep
    k_xT<<<(CIN_M * CIN_F0 + 255) / 256, 256>>>(x, xT);
    k_wp<<<1024, 256>>>(W0, wp_0, 64);
    k_wp<<<2048, 256>>>(W1, wp_1, 128);
    k_wp<<<2048, 256>>>(W2, wp_2, 128);

    // Fused 3-layer GEMM + reduction (grid = 256 tiles)
    cin_fused<<<CIN_M / 128, 256, smemF>>>(xT, wp_0, wp_1, wp_2, out);
}